// round 15
// baseline (speedup 1.0000x reference)
#include <cuda_runtime.h>
#include <cuda_fp16.h>
#include <cstdint>

#define NL 4
#define TT 64
#define QUADS 4
#define THREADS (QUADS * 128)        // 512: 4 quads x 4 warps; 32 rows per quad
#define ROWS_CTA (QUADS * 32)        // 128
#define BTOT 16384

// SMEM offsets
#define OFF_HX   65536u              // QUADS * NL * 4KB (2 bufs x 2KB) = 65536
#define OFF_RED  131072u             // QUADS * 512B
#define DSMEM    (131072 + 2048 + 64)

// staged data (built by prep_kernel)
__device__ uint32_t gBF[16384];      // fp16 W fragments [l][kc][nt][lane][word] (64KB)
__device__ float    gBiasF[512];
__device__ float    gWl[32];
__device__ float    gBl;

// ---------------- helpers ----------------
__device__ __forceinline__ uint32_t smem_u32(const void* p) {
    uint32_t a;
    asm("{ .reg .u64 t; cvta.to.shared.u64 t, %1; cvt.u32.u64 %0, t; }" : "=r"(a) : "l"(p));
    return a;
}
__device__ __forceinline__ void mma16816(float d[4], const uint32_t a[4], uint32_t b0, uint32_t b1) {
    asm volatile("mma.sync.aligned.m16n8k16.row.col.f32.f16.f16.f32 "
                 "{%0,%1,%2,%3}, {%4,%5,%6,%7}, {%8,%9}, {%0,%1,%2,%3};"
                 : "+f"(d[0]), "+f"(d[1]), "+f"(d[2]), "+f"(d[3])
                 : "r"(a[0]), "r"(a[1]), "r"(a[2]), "r"(a[3]), "r"(b0), "r"(b1));
}
__device__ __forceinline__ void lds64(uint32_t& a, uint32_t& b, uint32_t addr) {
    asm volatile("ld.shared.v2.u32 {%0,%1}, [%2];" : "=r"(a), "=r"(b) : "r"(addr));
}
__device__ __forceinline__ void ldf4(uint32_t* f, uint32_t addr) {
    asm volatile("ld.shared.v4.u32 {%0,%1,%2,%3}, [%4];"
                 : "=r"(f[0]), "=r"(f[1]), "=r"(f[2]), "=r"(f[3]) : "r"(addr));
}
__device__ __forceinline__ void stv2(uint32_t addr, uint32_t a, uint32_t b) {
    asm volatile("st.shared.v2.u32 [%0], {%1,%2};" :: "r"(addr), "r"(a), "r"(b) : "memory");
}
__device__ __forceinline__ void stsf(uint32_t addr, float v) {
    asm volatile("st.shared.f32 [%0], %1;" :: "r"(addr), "f"(v) : "memory");
}
__device__ __forceinline__ float ldsf(uint32_t addr) {
    float v; asm volatile("ld.shared.f32 %0, [%1];" : "=f"(v) : "r"(addr)); return v;
}
#define BARQ(id) asm volatile("bar.sync %0, 128;" :: "r"(id) : "memory")

__device__ __forceinline__ uint32_t pk2h(float a, float b) {
    __half2 t = __floats2half2_rn(a, b);
    return *(uint32_t*)&t;
}
__device__ __forceinline__ uint32_t tanh2(uint32_t v) {
    uint32_t r; asm("tanh.approx.f16x2 %0, %1;" : "=r"(r) : "r"(v)); return r;
}
__device__ __forceinline__ float lo2f(uint32_t v) { return __low2float(*(__half2*)&v); }
__device__ __forceinline__ float hi2f(uint32_t v) { return __high2float(*(__half2*)&v); }
__device__ __forceinline__ uint32_t hmul2u(uint32_t a, uint32_t b) {
    __half2 r = __hmul2(*(__half2*)&a, *(__half2*)&b);
    return *(uint32_t*)&r;
}
__device__ __forceinline__ uint32_t hfma2u(uint32_t a, uint32_t b, uint32_t c) {
    __half2 r = __hfma2(*(__half2*)&a, *(__half2*)&b, *(__half2*)&c);
    return *(uint32_t*)&r;
}
__device__ __forceinline__ float sigm_ex(float v) {
    return __fdividef(1.f, 1.f + __expf(-v));
}

// ---------------- prep (light) ----------------
__device__ __forceinline__ float getW(const float* W_ih0, const float* W_ih, const float* W_hh,
                                      int l, int n, int k) {
    if (k < 32) {
        if (l == 0) return (k < 2) ? W_ih0[n * 2 + k] : 0.f;
        return W_ih[(l - 1) * 4096 + n * 32 + k];
    }
    return W_hh[l * 4096 + n * 32 + (k - 32)];
}

__global__ void prep_kernel(const float* __restrict__ W_ih0, const float* __restrict__ W_ih,
                            const float* __restrict__ W_hh, const float* __restrict__ b_ih,
                            const float* __restrict__ b_hh, const float* __restrict__ W_lin,
                            const float* __restrict__ b_lin) {
    int i = blockIdx.x * blockDim.x + threadIdx.x;
    if (i < 16384) {
        int word = i & 1, lane = (i >> 1) & 31, nt = (i >> 6) & 15, kc = (i >> 10) & 3, l = i >> 12;
        int n  = nt * 8 + (lane >> 2);
        int k0 = kc * 16 + (lane & 3) * 2 + word * 8;
        float w0 = getW(W_ih0, W_ih, W_hh, l, n, k0);
        float w1 = getW(W_ih0, W_ih, W_hh, l, n, k0 + 1);
        gBF[i] = pk2h(w0, w1);
    }
    if (i < 512) {
        int e = i & 1, q = (i >> 1) & 3, nt = (i >> 3) & 15, l = i >> 7;
        int n = nt * 8 + q * 2 + e;
        gBiasF[i] = b_ih[l * 128 + n] + b_hh[l * 128 + n];
    }
    if (i < 32) gWl[i] = W_lin[i];
    if (i == 0) gBl = b_lin[0];
}

// ---------------- main kernel ----------------
__global__ void __launch_bounds__(THREADS, 1)
lstm_kernel(const float* __restrict__ x, float* __restrict__ out) {
    extern __shared__ __align__(16) uint4 smemraw[];
    const uint32_t smB  = smem_u32(smemraw);
    const uint32_t hxB  = smB + OFF_HX;
    const uint32_t redB = smB + OFF_RED;

    const int tid  = threadIdx.x;
    const int w    = tid >> 5;
    const int lane = tid & 31;
    const int q    = lane & 3;
    const int r    = lane >> 2;
    const int qd   = w >> 2;            // quad id (owns 32 rows)
    const int jt   = w & 3;             // hidden-col octet (8 cols, all 4 gates)
    const int jl   = jt & 1;            // position within 16-col chunk
    const int ch2  = jt >> 1;           // which 16-col chunk this warp writes
    const int bid  = 1 + qd;            // named barrier id
    const int gb0  = blockIdx.x * ROWS_CTA + qd * 32;
    const uint32_t lane16 = (uint32_t)lane * 16u;

    // ---- stage weights into SMEM; zero hx ----
    {
        const uint4* src = (const uint4*)gBF;
        uint4* dst = (uint4*)smemraw;
        for (int i = tid; i < 4096; i += THREADS) dst[i] = src[i];
        uint4* hz = (uint4*)((char*)smemraw + OFF_HX);
        for (int i = tid; i < 65536 / 16; i += THREADS) hz[i] = make_uint4(0, 0, 0, 0);
    }
    __syncthreads();

    // ---- bias pre-scaled into 16 half2 registers: bias2[l][g4] ----
    uint32_t bias2[NL][4];
#pragma unroll
    for (int l = 0; l < NL; ++l)
#pragma unroll
        for (int g4 = 0; g4 < 4; ++g4) {
            int idx = (((l * 16 + g4 * 4 + jt) * 4 + q) * 2);
            float s = (g4 == 2) ? 1.0f : 0.5f;
            bias2[l][g4] = pk2h(s * __ldg(gBiasF + idx), s * __ldg(gBiasF + idx + 1));
        }

    float cst[NL][2][4];                 // [l][mt][p]
#pragma unroll
    for (int l = 0; l < NL; ++l)
#pragma unroll
        for (int mt = 0; mt < 2; ++mt)
#pragma unroll
            for (int p = 0; p < 4; ++p) cst[l][mt][p] = 0.f;

    float wl0 = gWl[jt * 8 + q * 2];
    float wl1 = gWl[jt * 8 + q * 2 + 1];

    float prow[2][2] = {{0.f, 0.f}, {0.f, 0.f}};     // [mt][r / r+8]
    const uint32_t hxQuad = hxB + (uint32_t)qd * 16384u;   // 4 layers x 4KB
    const uint32_t h05 = pk2h(0.5f, 0.5f);
    const uint32_t h10 = pk2h(1.0f, 1.0f);
    const float* xq = x + (size_t)gb0 * 192;

#pragma unroll 1
    for (int t = 0; t < TT; ++t) {
        const uint32_t sW = (uint32_t)(t & 1) * 2048u;       // write buf
        const uint32_t sR = sW ^ 2048u;                      // h_prev read buf

        // ---- x fragments (layer 0, kc0), two m-tiles; q==0 lanes hold k=0,1 ----
        uint32_t AX[2][4];
#pragma unroll
        for (int mt = 0; mt < 2; ++mt) {
            AX[mt][0] = 0u; AX[mt][1] = 0u; AX[mt][2] = 0u; AX[mt][3] = 0u;
        }
        if (q == 0) {
#pragma unroll
            for (int mt = 0; mt < 2; ++mt) {
                const float* xr = xq + (size_t)(mt * 16 + r) * 192 + t;
                AX[mt][0] = pk2h(__ldg(xr),        __ldg(xr + 64));
                AX[mt][1] = pk2h(__ldg(xr + 1536), __ldg(xr + 1600));   // row +8
            }
        }

#pragma unroll
        for (int l = 0; l < NL; ++l) {
            const uint32_t hxL = hxQuad + (uint32_t)l * 4096u;
            const uint32_t bL  = smB + (uint32_t)l * 16384u + (uint32_t)lane * 8u;

            float d[2][4][4];                // [mt][g4][p]
#pragma unroll
            for (int mt = 0; mt < 2; ++mt)
#pragma unroll
                for (int g4 = 0; g4 < 4; ++g4)
#pragma unroll
                    for (int p = 0; p < 4; ++p) d[mt][g4][p] = 0.f;

            // chunk-serial A loads (8 regs live)
#pragma unroll
            for (int c = 0; c < 4; ++c) {
                uint32_t A0[4], A1[4];
                if (c < 2) {
                    if (l == 0) {
                        if (c == 1) continue;          // l0: only x chunk (kc0)
#pragma unroll
                        for (int u = 0; u < 4; ++u) { A0[u] = AX[0][u]; A1[u] = AX[1][u]; }
                    } else {
                        const uint32_t base = hxQuad + (uint32_t)(l - 1) * 4096u + sW;
                        ldf4(A0, base + (uint32_t)(c * 1024)       + lane16);
                        ldf4(A1, base + (uint32_t)(c * 1024 + 512) + lane16);
                    }
                } else {
                    ldf4(A0, hxL + sR + (uint32_t)((c - 2) * 1024)       + lane16);
                    ldf4(A1, hxL + sR + (uint32_t)((c - 2) * 1024 + 512) + lane16);
                }
#pragma unroll
                for (int g4 = 0; g4 < 4; ++g4) {
                    uint32_t b0, b1;
                    lds64(b0, b1, bL + (uint32_t)(c * 4096 + (g4 * 4 + jt) * 256));
                    mma16816(d[0][g4], A0, b0, b1);
                    mma16816(d[1][g4], A1, b0, b1);
                }
            }

            // ---- f16x2 epilogue, both m-tiles; cell complete within warp ----
#pragma unroll
            for (int mt = 0; mt < 2; ++mt) {
                uint32_t fr[2];
#pragma unroll
                for (int pr = 0; pr < 2; ++pr) {
                    const int p0 = pr * 2;
                    uint32_t ti = tanh2(hfma2u(pk2h(d[mt][0][p0], d[mt][0][p0 + 1]), h05, bias2[l][0]));
                    uint32_t tf = tanh2(hfma2u(pk2h(d[mt][1][p0], d[mt][1][p0 + 1]), h05, bias2[l][1]));
                    uint32_t tg = tanh2(hfma2u(pk2h(d[mt][2][p0], d[mt][2][p0 + 1]), h10, bias2[l][2]));
                    uint32_t to = tanh2(hfma2u(pk2h(d[mt][3][p0], d[mt][3][p0 + 1]), h05, bias2[l][3]));
                    float i0 = fmaf(0.5f, lo2f(ti), 0.5f), i1 = fmaf(0.5f, hi2f(ti), 0.5f);
                    float f0 = fmaf(0.5f, lo2f(tf), 0.5f), f1 = fmaf(0.5f, hi2f(tf), 0.5f);
                    float g0 = lo2f(tg), g1 = hi2f(tg);
                    float c0 = fmaf(f0, cst[l][mt][p0],     i0 * g0);
                    float c1 = fmaf(f1, cst[l][mt][p0 + 1], i1 * g1);
                    cst[l][mt][p0]     = c0;
                    cst[l][mt][p0 + 1] = c1;
                    uint32_t tc = tanh2(pk2h(c0, c1));
                    uint32_t o2 = hfma2u(to, h05, h05);
                    uint32_t h2 = hmul2u(o2, tc);
                    fr[pr] = h2;
                    if (l == NL - 1 && t == TT - 1) {
                        prow[mt][pr] = fmaf(lo2f(h2), wl0, prow[mt][pr]);
                        prow[mt][pr] = fmaf(hi2f(h2), wl1, prow[mt][pr]);
                    }
                }
                // publish this warp's 8B slice of the fragment line
                stv2(hxL + sW + (uint32_t)(ch2 * 1024 + mt * 512) + lane16 + (uint32_t)(jl * 8),
                     fr[0], fr[1]);
            }
            BARQ(bid);
        }
    }

    // ---- head: out = sigmoid(h3 . Wlin + b) ----
#pragma unroll
    for (int mt = 0; mt < 2; ++mt)
#pragma unroll
        for (int hb = 0; hb < 2; ++hb) {
            prow[mt][hb] += __shfl_xor_sync(0xffffffffu, prow[mt][hb], 1);
            prow[mt][hb] += __shfl_xor_sync(0xffffffffu, prow[mt][hb], 2);
        }
    const uint32_t redP = redB + (uint32_t)(qd * 512);
    if (q == 0) {
#pragma unroll
        for (int mt = 0; mt < 2; ++mt) {
            stsf(redP + (uint32_t)(jt * 128 + (mt * 16 + r) * 4),     prow[mt][0]);
            stsf(redP + (uint32_t)(jt * 128 + (mt * 16 + r + 8) * 4), prow[mt][1]);
        }
    }
    BARQ(bid);
    if (jt == 0 && q == 0) {
        float bl = gBl;
#pragma unroll
        for (int mt = 0; mt < 2; ++mt) {
#pragma unroll
            for (int hb = 0; hb < 2; ++hb) {
                int row = mt * 16 + r + hb * 8;
                float v = ldsf(redP + (uint32_t)(row * 4))
                        + ldsf(redP + (uint32_t)(128 + row * 4))
                        + ldsf(redP + (uint32_t)(256 + row * 4))
                        + ldsf(redP + (uint32_t)(384 + row * 4));
                out[gb0 + row] = sigm_ex(v + bl);
            }
        }
    }
}

extern "C" void kernel_launch(void* const* d_in, const int* in_sizes, int n_in,
                              void* d_out, int out_size) {
    const float* x     = (const float*)d_in[0];
    const float* W_ih0 = (const float*)d_in[1];
    const float* W_ih  = (const float*)d_in[2];
    const float* W_hh  = (const float*)d_in[3];
    const float* b_ih  = (const float*)d_in[4];
    const float* b_hh  = (const float*)d_in[5];
    const float* W_lin = (const float*)d_in[6];
    const float* b_lin = (const float*)d_in[7];

    prep_kernel<<<64, 256>>>(W_ih0, W_ih, W_hh, b_ih, b_hh, W_lin, b_lin);

    cudaFuncSetAttribute(lstm_kernel, cudaFuncAttributeMaxDynamicSharedMemorySize, DSMEM);

    int blocks = BTOT / ROWS_CTA;    // 128
    lstm_kernel<<<blocks, THREADS, DSMEM>>>(x, (float*)d_out);
}

// round 16
// speedup vs baseline: 1.2597x; 1.2597x over previous
#include <cuda_runtime.h>
#include <cuda_fp16.h>
#include <cstdint>

#define NL 4
#define TT 64
#define WARPS 8
#define THREADS (WARPS * 32)        // 256: each warp owns 16 rows end-to-end
#define ROWS_CTA (WARPS * 16)       // 128
#define BTOT 16384

// SMEM: weights 64KB + bias 1KB
#define OFF_BIAS 65536u
#define DSMEM    (65536 + 1024 + 64)

// staged data (built by prep_kernel)
__device__ uint32_t gBF[16384];      // fp16 W fragments [l][kc][nt][lane][word] (64KB)
__device__ float    gBiasF[512];
__device__ float    gWl[32];
__device__ float    gBl;

// ---------------- helpers ----------------
__device__ __forceinline__ uint32_t smem_u32(const void* p) {
    uint32_t a;
    asm("{ .reg .u64 t; cvta.to.shared.u64 t, %1; cvt.u32.u64 %0, t; }" : "=r"(a) : "l"(p));
    return a;
}
__device__ __forceinline__ void mma16816(float d[4], const uint32_t a[4], uint32_t b0, uint32_t b1) {
    asm volatile("mma.sync.aligned.m16n8k16.row.col.f32.f16.f16.f32 "
                 "{%0,%1,%2,%3}, {%4,%5,%6,%7}, {%8,%9}, {%0,%1,%2,%3};"
                 : "+f"(d[0]), "+f"(d[1]), "+f"(d[2]), "+f"(d[3])
                 : "r"(a[0]), "r"(a[1]), "r"(a[2]), "r"(a[3]), "r"(b0), "r"(b1));
}
__device__ __forceinline__ void lds64(uint32_t& a, uint32_t& b, uint32_t addr) {
    asm volatile("ld.shared.v2.u32 {%0,%1}, [%2];" : "=r"(a), "=r"(b) : "r"(addr));
}
__device__ __forceinline__ uint32_t lds32(uint32_t addr) {
    uint32_t v; asm volatile("ld.shared.b32 %0, [%1];" : "=r"(v) : "r"(addr)); return v;
}
__device__ __forceinline__ uint32_t pk2h(float a, float b) {
    __half2 t = __floats2half2_rn(a, b);
    return *(uint32_t*)&t;
}
__device__ __forceinline__ uint32_t tanh2(uint32_t v) {
    uint32_t r; asm("tanh.approx.f16x2 %0, %1;" : "=r"(r) : "r"(v)); return r;
}
__device__ __forceinline__ float lo2f(uint32_t v) { return __low2float(*(__half2*)&v); }
__device__ __forceinline__ float hi2f(uint32_t v) { return __high2float(*(__half2*)&v); }
__device__ __forceinline__ uint32_t hmul2u(uint32_t a, uint32_t b) {
    __half2 r = __hmul2(*(__half2*)&a, *(__half2*)&b);
    return *(uint32_t*)&r;
}
__device__ __forceinline__ uint32_t hfma2u(uint32_t a, uint32_t b, uint32_t c) {
    __half2 r = __hfma2(*(__half2*)&a, *(__half2*)&b, *(__half2*)&c);
    return *(uint32_t*)&r;
}
__device__ __forceinline__ float sigm_ex(float v) {
    return __fdividef(1.f, 1.f + __expf(-v));
}

// ---------------- prep (unchanged layouts) ----------------
__device__ __forceinline__ float getW(const float* W_ih0, const float* W_ih, const float* W_hh,
                                      int l, int n, int k) {
    if (k < 32) {
        if (l == 0) return (k < 2) ? W_ih0[n * 2 + k] : 0.f;
        return W_ih[(l - 1) * 4096 + n * 32 + k];
    }
    return W_hh[l * 4096 + n * 32 + (k - 32)];
}

__global__ void prep_kernel(const float* __restrict__ W_ih0, const float* __restrict__ W_ih,
                            const float* __restrict__ W_hh, const float* __restrict__ b_ih,
                            const float* __restrict__ b_hh, const float* __restrict__ W_lin,
                            const float* __restrict__ b_lin) {
    int i = blockIdx.x * blockDim.x + threadIdx.x;
    if (i < 16384) {
        int word = i & 1, lane = (i >> 1) & 31, nt = (i >> 6) & 15, kc = (i >> 10) & 3, l = i >> 12;
        int n  = nt * 8 + (lane >> 2);
        int k0 = kc * 16 + (lane & 3) * 2 + word * 8;
        float w0 = getW(W_ih0, W_ih, W_hh, l, n, k0);
        float w1 = getW(W_ih0, W_ih, W_hh, l, n, k0 + 1);
        gBF[i] = pk2h(w0, w1);
    }
    if (i < 512) {
        int e = i & 1, q = (i >> 1) & 3, nt = (i >> 3) & 15, l = i >> 7;
        int n = nt * 8 + q * 2 + e;
        gBiasF[i] = b_ih[l * 128 + n] + b_hh[l * 128 + n];
    }
    if (i < 32) gWl[i] = W_lin[i];
    if (i == 0) gBl = b_lin[0];
}

// ---------------- main kernel ----------------
__global__ void __launch_bounds__(THREADS, 1)
lstm_kernel(const float* __restrict__ x, float* __restrict__ out) {
    extern __shared__ __align__(16) uint4 smemraw[];
    const uint32_t smB   = smem_u32(smemraw);
    const uint32_t biasB = smB + OFF_BIAS;

    const int tid  = threadIdx.x;
    const int w    = tid >> 5;
    const int lane = tid & 31;
    const int q    = lane & 3;
    const int r    = lane >> 2;
    const int gb0  = blockIdx.x * ROWS_CTA + w * 16;

    // ---- stage weights + prescaled half2 bias into SMEM ----
    {
        const uint4* src = (const uint4*)gBF;
        uint4* dst = (uint4*)smemraw;
        for (int i = tid; i < 4096; i += THREADS) dst[i] = src[i];
        if (tid < 256) {
            int nt = (tid >> 2) & 15;
            float s = ((nt >> 2) == 2) ? 1.0f : 0.5f;   // g-gate tiles (nt 8..11) unscaled
            ((uint32_t*)((char*)smemraw + OFF_BIAS))[tid] =
                pk2h(s * gBiasF[tid * 2], s * gBiasF[tid * 2 + 1]);
        }
    }
    __syncthreads();

    // h A-fragments per layer, register-resident: hA[l][ch][rr]
    // rr: [k0-7 row r], [k0-7 row r+8], [k8-15 row r], [k8-15 row r+8] (R7-validated)
    uint32_t hA[NL][2][4];
#pragma unroll
    for (int l = 0; l < NL; ++l)
#pragma unroll
        for (int ch = 0; ch < 2; ++ch)
#pragma unroll
            for (int rr = 0; rr < 4; ++rr) hA[l][ch][rr] = 0u;

    float cst[NL][4][4];     // [l][jtc][p]  (p = pr*2 + col parity)
#pragma unroll
    for (int l = 0; l < NL; ++l)
#pragma unroll
        for (int jtc = 0; jtc < 4; ++jtc)
#pragma unroll
            for (int p = 0; p < 4; ++p) cst[l][jtc][p] = 0.f;

    const uint32_t h05 = pk2h(0.5f, 0.5f);
    const uint32_t h10 = pk2h(1.0f, 1.0f);
    const float* xq = x + (size_t)(gb0 + r) * 192;

#pragma unroll 1
    for (int t = 0; t < TT; ++t) {
        // ---- x fragment (layer 0, kc0): k=0,1 live in q==0 lanes ----
        uint32_t ax[4] = {0u, 0u, 0u, 0u};
        if (q == 0) {
            ax[0] = pk2h(__ldg(xq + t),        __ldg(xq + 64 + t));          // row r
            ax[1] = pk2h(__ldg(xq + 1536 + t), __ldg(xq + 1600 + t));        // row r+8
        }

#pragma unroll
        for (int l = 0; l < NL; ++l) {
            const uint32_t bL = smB + (uint32_t)l * 16384u + (uint32_t)lane * 8u;

            float d[16][4];
#pragma unroll
            for (int nt = 0; nt < 16; ++nt)
#pragma unroll
                for (int p = 0; p < 4; ++p) d[nt][p] = 0.f;

            // ---- MMAs: 16 n-tiles x k-chunks, all A in registers ----
#pragma unroll
            for (int kc = 0; kc < 4; ++kc) {
                const uint32_t* A;
                if (kc < 2) {
                    if (l == 0) {
                        if (kc == 1) continue;       // l0: zero-padded ih cols 16..31
                        A = ax;
                    } else {
                        A = hA[l - 1][kc];           // h_in (just produced this step)
                    }
                } else {
                    A = hA[l][kc - 2];               // h_prev (from step t-1)
                }
#pragma unroll
                for (int nt = 0; nt < 16; ++nt) {
                    uint32_t b0, b1;
                    lds64(b0, b1, bL + (uint32_t)(kc * 4096 + nt * 256));
                    mma16816(d[nt], A, b0, b1);
                }
            }

            // ---- f16x2 epilogue; h goes straight back into A-fragments ----
#pragma unroll
            for (int jtc = 0; jtc < 4; ++jtc) {
                const uint32_t bb = biasB + (uint32_t)((l * 64 + jtc * 4 + q) * 4);
                uint32_t bi = lds32(bb);
                uint32_t bf = lds32(bb + 64u);
                uint32_t bg = lds32(bb + 128u);
                uint32_t bo = lds32(bb + 192u);
#pragma unroll
                for (int pr = 0; pr < 2; ++pr) {
                    const int p0 = pr * 2;
                    uint32_t ti = tanh2(hfma2u(pk2h(d[0 * 4 + jtc][p0], d[0 * 4 + jtc][p0 + 1]), h05, bi));
                    uint32_t tf = tanh2(hfma2u(pk2h(d[1 * 4 + jtc][p0], d[1 * 4 + jtc][p0 + 1]), h05, bf));
                    uint32_t tg = tanh2(hfma2u(pk2h(d[2 * 4 + jtc][p0], d[2 * 4 + jtc][p0 + 1]), h10, bg));
                    uint32_t to = tanh2(hfma2u(pk2h(d[3 * 4 + jtc][p0], d[3 * 4 + jtc][p0 + 1]), h05, bo));
                    float i0 = fmaf(0.5f, lo2f(ti), 0.5f), i1 = fmaf(0.5f, hi2f(ti), 0.5f);
                    float f0 = fmaf(0.5f, lo2f(tf), 0.5f), f1 = fmaf(0.5f, hi2f(tf), 0.5f);
                    float g0 = lo2f(tg), g1 = hi2f(tg);
                    float c0 = fmaf(f0, cst[l][jtc][p0],     i0 * g0);
                    float c1 = fmaf(f1, cst[l][jtc][p0 + 1], i1 * g1);
                    cst[l][jtc][p0]     = c0;
                    cst[l][jtc][p0 + 1] = c1;
                    uint32_t tc = tanh2(pk2h(c0, c1));
                    uint32_t o2 = hfma2u(to, h05, h05);
                    // D(row-group pr, cols 2q,2q+1 of block jtc) == A reg (jtc&1)*2+pr of chunk jtc>>1
                    hA[l][jtc >> 1][(jtc & 1) * 2 + pr] = hmul2u(o2, tc);
                }
            }
        }
    }

    // ---- head (warp-local): out = sigmoid(h3 . Wlin + b) ----
    float prow[2] = {0.f, 0.f};
#pragma unroll
    for (int ch = 0; ch < 2; ++ch)
#pragma unroll
        for (int rr = 0; rr < 4; ++rr) {
            int jtc = ch * 2 + (rr >> 1);
            int pr  = rr & 1;
            uint32_t h2 = hA[NL - 1][ch][rr];
            float w0 = __ldg(gWl + jtc * 8 + q * 2);
            float w1 = __ldg(gWl + jtc * 8 + q * 2 + 1);
            prow[pr] = fmaf(lo2f(h2), w0, prow[pr]);
            prow[pr] = fmaf(hi2f(h2), w1, prow[pr]);
        }
#pragma unroll
    for (int pr = 0; pr < 2; ++pr) {
        prow[pr] += __shfl_xor_sync(0xffffffffu, prow[pr], 1);
        prow[pr] += __shfl_xor_sync(0xffffffffu, prow[pr], 2);
    }
    if (q == 0) {
        float bl = gBl;
        out[gb0 + r]     = sigm_ex(prow[0] + bl);
        out[gb0 + r + 8] = sigm_ex(prow[1] + bl);
    }
}

extern "C" void kernel_launch(void* const* d_in, const int* in_sizes, int n_in,
                              void* d_out, int out_size) {
    const float* x     = (const float*)d_in[0];
    const float* W_ih0 = (const float*)d_in[1];
    const float* W_ih  = (const float*)d_in[2];
    const float* W_hh  = (const float*)d_in[3];
    const float* b_ih  = (const float*)d_in[4];
    const float* b_hh  = (const float*)d_in[5];
    const float* W_lin = (const float*)d_in[6];
    const float* b_lin = (const float*)d_in[7];

    prep_kernel<<<64, 256>>>(W_ih0, W_ih, W_hh, b_ih, b_hh, W_lin, b_lin);

    cudaFuncSetAttribute(lstm_kernel, cudaFuncAttributeMaxDynamicSharedMemorySize, DSMEM);

    int blocks = BTOT / ROWS_CTA;    // 128
    lstm_kernel<<<blocks, THREADS, DSMEM>>>(x, (float*)d_out);
}